// round 1
// baseline (speedup 1.0000x reference)
#include <cuda_runtime.h>
#include <math.h>

#define BATCH 4
#define DIMC  64
#define HFC   128
#define C2C   256
#define HH    256
#define WWC   256
#define HW    (HH*WWC)   // 65536

// ---------------- scratch (device globals: allocation-free rule) -------------
__device__ float g_h[(size_t)BATCH*C2C*HW];   // in-proj output  (268 MB)
__device__ float g_u[(size_t)BATCH*C2C*HW];   // spectral output (268 MB)
__device__ float g_g[(size_t)BATCH*HFC*HW];   // gated output    (134 MB)
__device__ float g_sk[C2C*64];                // per-channel 8x8 spatial kernels

// ---------------- packed fp32x2 helpers (sm_100+ PTX) ------------------------
typedef unsigned long long u64;
__device__ __forceinline__ u64 pk(float lo, float hi){
    u64 r; asm("mov.b64 %0, {%1,%2};" : "=l"(r) : "f"(lo), "f"(hi)); return r;
}
__device__ __forceinline__ float2 upk(u64 v){
    float2 r; asm("mov.b64 {%0,%1}, %2;" : "=f"(r.x), "=f"(r.y) : "l"(v)); return r;
}
__device__ __forceinline__ void fma2(u64& d, u64 a, u64 b){
    asm("fma.rn.f32x2 %0, %1, %2, %0;" : "+l"(d) : "l"(a), "l"(b));
}

// ---------------- K0: spectral filter -> spatial 8x8 circular kernel ---------
// g_c[n1,n2] = (1/64) * sum_{k1,k2=0..7} G(k1,k2) cos(pi/4*(k1*n1+k2*n2))
// G: Hermitian extension of F with symmetrization at k2 in {0,4}
// (matches pocketfft/cuFFT c2r dropping Im at bins 0 and N/2).
__global__ void k0_spectral(const float* __restrict__ filt){
    int c  = blockIdx.x;
    int n1 = threadIdx.x >> 3, n2 = threadIdx.x & 7;
    const float* F = filt + c*40;   // [8][5]
    float s = 0.f;
    for (int k1=0;k1<8;k1++){
        for (int k2=0;k2<8;k2++){
            float Gv;
            if (k2>=1 && k2<=3)      Gv = F[k1*5+k2];
            else if (k2>=5)          Gv = F[((8-k1)&7)*5 + (8-k2)];
            else                     Gv = 0.5f*(F[k1*5+k2] + F[((8-k1)&7)*5 + k2]);
            int m = (k1*n1 + k2*n2) & 7;
            s += Gv * cospif(0.25f * (float)m);
        }
    }
    g_sk[c*64 + threadIdx.x] = s * (1.f/64.f);
}

// ---------------- K1: in-projection  h[b,o,p] = sum_c w_in[o,c]*x[b,c,p] -----
// block: 256 threads = 256 pixels; 64 output channels per block (paired f32x2).
__global__ void k1_inproj(const float* __restrict__ x, const float* __restrict__ w_in){
    extern __shared__ float sm[];
    float* xs  = sm;                   // [64][256]
    u64*   wpk = (u64*)(sm + 64*256);  // [64][32]  (channel-pair packed)
    int b = blockIdx.z, og = blockIdx.y;     // og*64 = output-channel base
    int pix0 = blockIdx.x * 256;
    int t = threadIdx.x;

    for (int i=t; i<64*32; i+=256){
        int c = i>>5, j = i&31;
        int o = og*64 + 2*j;
        wpk[i] = pk(w_in[o*64 + c], w_in[(o+1)*64 + c]);
    }
    const float* xb = x + (size_t)b*DIMC*HW + pix0;
    for (int i=t; i<64*256; i+=256){
        int c = i>>8, p = i&255;
        xs[i] = xb[(size_t)c*HW + p];
    }
    __syncthreads();

    u64 acc[32];
    #pragma unroll
    for (int j=0;j<32;j++) acc[j]=0ULL;
    #pragma unroll 8
    for (int c=0;c<64;c++){
        float xv = xs[c*256 + t];
        u64 xp = pk(xv, xv);
        const u64* wr = &wpk[c*32];
        #pragma unroll
        for (int j=0;j<32;j++) fma2(acc[j], xp, wr[j]);
    }
    float* hb = g_h + (size_t)(b*C2C + og*64)*HW + pix0;
    #pragma unroll
    for (int j=0;j<32;j++){
        float2 v = upk(acc[j]);
        hb[(size_t)(2*j)  *HW + t] = v.x;
        hb[(size_t)(2*j+1)*HW + t] = v.y;
    }
}

// ---------------- K2: patchwise 8x8 circular convolution ---------------------
// block: (patch-row, channel, batch); 256 threads: thread t -> col t of 8-row strip.
__global__ void k2_spec(){
    __shared__ __align__(16) float xs[8*256];
    __shared__ float gsh[64];
    __shared__ u64 gp[256];   // [(a*4+q)*8 + n2]: pair (g[a][(n2-2q)&7], g[a][(n2-2q-1)&7])
    int pr = blockIdx.x, c = blockIdx.y, b = blockIdx.z;
    int t = threadIdx.x;
    const float* hb = g_h + (size_t)(b*C2C + c)*HW + pr*8*WWC;
    for (int i=t;i<2048;i+=256) xs[i] = hb[i];
    if (t < 64) gsh[t] = g_sk[c*64 + t];
    __syncthreads();
    {
        int a = t>>5, q=(t>>3)&3, n2i=t&7;
        gp[(a*4+q)*8+n2i] = pk(gsh[a*8+((n2i-2*q)&7)], gsh[a*8+((n2i-2*q-1)&7)]);
    }
    __syncthreads();

    int p = t>>3, n2 = t&7;
    u64 xp[32];
    #pragma unroll
    for (int m1=0;m1<8;m1++)
        #pragma unroll
        for (int q=0;q<4;q++){
            float2 v = *(const float2*)&xs[m1*256 + p*8 + 2*q];
            xp[m1*4+q] = pk(v.x, v.y);
        }
    u64 acc[8];
    #pragma unroll
    for (int n=0;n<8;n++) acc[n]=0ULL;
    #pragma unroll
    for (int m1=0;m1<8;m1++){
        #pragma unroll
        for (int q=0;q<4;q++){
            u64 xv = xp[m1*4+q];
            #pragma unroll
            for (int n1=0;n1<8;n1++){
                int a = (n1 - m1) & 7;
                fma2(acc[n1], xv, gp[(a*4+q)*8 + n2]);
            }
        }
    }
    float* ub = g_u + (size_t)(b*C2C + c)*HW + pr*8*WWC;
    #pragma unroll
    for (int n1=0;n1<8;n1++){
        float2 v = upk(acc[n1]);
        ub[n1*WWC + t] = v.x + v.y;
    }
}

// ---------------- K3: depthwise 3x3 (SAME, zero pad) + exact GELU gate -------
__global__ void k3_dwgelu(const float* __restrict__ w_dw){
    __shared__ float su[2][18][256];
    int yt = blockIdx.x, i = blockIdx.y, b = blockIdx.z;
    int t = threadIdx.x;
    int y0 = yt*16;
    const float* u1 = g_u + (size_t)(b*C2C + i)*HW;
    const float* u2 = g_u + (size_t)(b*C2C + i + HFC)*HW;
    for (int idx=t; idx<2*18*256; idx+=256){
        int ch = idx / (18*256);
        int rr = (idx/256) % 18;
        int xx = idx & 255;
        int y = y0 + rr - 1;
        const float* up = ch ? u2 : u1;
        su[ch][rr][xx] = (y>=0 && y<HH) ? up[y*WWC + xx] : 0.f;
    }
    __syncthreads();
    float wA[9], wB[9];
    #pragma unroll
    for (int k=0;k<9;k++){ wA[k]=w_dw[i*9+k]; wB[k]=w_dw[(i+HFC)*9+k]; }
    int xx = t;
    float* gb = g_g + (size_t)(b*HFC + i)*HW;
    for (int r=0;r<16;r++){
        float d1=0.f, d2=0.f;
        #pragma unroll
        for (int dy=0;dy<3;dy++){
            #pragma unroll
            for (int dx=0;dx<3;dx++){
                int xc = xx + dx - 1;
                float v1 = (xc>=0 && xc<WWC) ? su[0][r+dy][xc] : 0.f;
                float v2 = (xc>=0 && xc<WWC) ? su[1][r+dy][xc] : 0.f;
                d1 = fmaf(wA[dy*3+dx], v1, d1);
                d2 = fmaf(wB[dy*3+dx], v2, d2);
            }
        }
        float ge = 0.5f*d1*(1.f + erff(d1*0.70710678118654752f));
        gb[(y0+r)*WWC + xx] = ge*d2;
    }
}

// ---------------- K4: out-projection out[b,o,p] = sum_i w_out[o,i]*g[b,i,p] --
__global__ void k4_outproj(float* __restrict__ out, const float* __restrict__ w_out){
    extern __shared__ float sm[];
    float* gs  = sm;                     // [128][256]
    u64*   wpk = (u64*)(sm + 128*256);   // [128][32]
    int b = blockIdx.y; int pix0 = blockIdx.x*256;
    int t = threadIdx.x;
    for (int idx=t; idx<128*32; idx+=256){
        int ii = idx>>5, j = idx&31;
        wpk[idx] = pk(w_out[(2*j)*HFC + ii], w_out[(2*j+1)*HFC + ii]);
    }
    const float* gb = g_g + (size_t)b*HFC*HW + pix0;
    for (int idx=t; idx<128*256; idx+=256){
        int ii = idx>>8, p = idx&255;
        gs[idx] = gb[(size_t)ii*HW + p];
    }
    __syncthreads();
    u64 acc[32];
    #pragma unroll
    for (int j=0;j<32;j++) acc[j]=0ULL;
    #pragma unroll 8
    for (int ii=0; ii<128; ii++){
        float xv = gs[ii*256 + t];
        u64 xp = pk(xv, xv);
        const u64* wr = &wpk[ii*32];
        #pragma unroll
        for (int j=0;j<32;j++) fma2(acc[j], xp, wr[j]);
    }
    float* ob = out + (size_t)b*DIMC*HW + pix0;
    #pragma unroll
    for (int j=0;j<32;j++){
        float2 v = upk(acc[j]);
        ob[(size_t)(2*j)  *HW + t] = v.x;
        ob[(size_t)(2*j+1)*HW + t] = v.y;
    }
}

// -----------------------------------------------------------------------------
extern "C" void kernel_launch(void* const* d_in, const int* in_sizes, int n_in,
                              void* d_out, int out_size){
    const float* x     = (const float*)d_in[0];
    const float* w_in  = (const float*)d_in[1];
    const float* w_dw  = (const float*)d_in[2];
    const float* filt  = (const float*)d_in[3];
    const float* w_out = (const float*)d_in[4];
    float* out = (float*)d_out;

    cudaFuncSetAttribute(k1_inproj,  cudaFuncAttributeMaxDynamicSharedMemorySize, 64*256*4 + 64*32*8);
    cudaFuncSetAttribute(k4_outproj, cudaFuncAttributeMaxDynamicSharedMemorySize, 128*256*4 + 128*32*8);

    k0_spectral<<<256, 64>>>(filt);
    k1_inproj  <<<dim3(256,4,4), 256, 64*256*4 + 64*32*8>>>(x, w_in);
    k2_spec    <<<dim3(32,256,4), 256>>>();
    k3_dwgelu  <<<dim3(16,128,4), 256>>>(w_dw);
    k4_outproj <<<dim3(256,4),   256, 128*256*4 + 128*32*8>>>(out, w_out);
}

// round 2
// speedup vs baseline: 1.8504x; 1.8504x over previous
#include <cuda_runtime.h>
#include <math.h>

#define BATCH 4
#define DIMC  64
#define HFC   128
#define C2C   256
#define HH    256
#define WWC   256
#define HW    (HH*WWC)   // 65536

// ---------------- scratch (device globals: allocation-free rule) -------------
__device__ float g_u[(size_t)BATCH*C2C*HW];         // spectral output (268 MB)
__device__ float g_g[(size_t)BATCH*HFC*HW];         // gated output    (134 MB)
__device__ unsigned long long g_pk[(size_t)C2C*8*32]; // packed spatial filter pairs

// ---------------- packed fp32x2 helpers (sm_100+ PTX) ------------------------
typedef unsigned long long u64;
__device__ __forceinline__ u64 pk(float lo, float hi){
    u64 r; asm("mov.b64 %0, {%1,%2};" : "=l"(r) : "f"(lo), "f"(hi)); return r;
}
__device__ __forceinline__ float2 upk(u64 v){
    float2 r; asm("mov.b64 {%0,%1}, %2;" : "=f"(r.x), "=f"(r.y) : "l"(v)); return r;
}
__device__ __forceinline__ void fma2(u64& d, u64 a, u64 b){
    asm("fma.rn.f32x2 %0, %1, %2, %0;" : "+l"(d) : "l"(a), "l"(b));
}

// ---------------- K0: spectral filter -> packed spatial 8x8 kernels ----------
// g_c[n1,n2] = (1/64) * sum_{k1,k2} G(k1,k2) cos(pi/4*(k1*n1+k2*n2)),
// G = Hermitian extension of F with symmetrization at k2 in {0,4}.
// Then pack pairs for the m2-paired fma2 conv:
//   g_pk[c][n2][a*4+q] = ( g[a][(n2-2q)&7], g[a][(n2-2q-1)&7] )
__global__ void k0_spectral(const float* __restrict__ filt){
    __shared__ float gs[64];
    int c = blockIdx.x, t = threadIdx.x;
    int n1 = t >> 3, n2 = t & 7;
    const float* F = filt + c*40;   // [8][5]
    float s = 0.f;
    for (int k1=0;k1<8;k1++){
        for (int k2=0;k2<8;k2++){
            float Gv;
            if (k2>=1 && k2<=3)      Gv = F[k1*5+k2];
            else if (k2>=5)          Gv = F[((8-k1)&7)*5 + (8-k2)];
            else                     Gv = 0.5f*(F[k1*5+k2] + F[((8-k1)&7)*5 + k2]);
            int m = (k1*n1 + k2*n2) & 7;
            s += Gv * cospif(0.25f * (float)m);
        }
    }
    gs[t] = s * (1.f/64.f);
    __syncthreads();
    for (int r=0;r<4;r++){
        int idx = r*64 + t;           // 0..255
        int nn2 = idx >> 5;
        int aq  = idx & 31;
        int a = aq >> 2, q = aq & 3;
        g_pk[((size_t)c*8 + nn2)*32 + aq] =
            pk(gs[a*8 + ((nn2-2*q)&7)], gs[a*8 + ((nn2-2*q-1)&7)]);
    }
}

// ---------------- K12: fused in-projection + patchwise circular conv ---------
// Block: spatial strip = rows [s*8, s*8+8) x cols [cg*64, cg*64+64) (512 px,
// 8 complete 8x8 patches), 32 output channels (blockIdx.y), batch blockIdx.z.
// Phase 1: GEMM h = W_in * x into registers (thread: 4 px x 16 oc).
// Phase 2: per-channel 8x8 circular conv from smem h tile, write u.
__global__ __launch_bounds__(256) void k12_fused(const float* __restrict__ x,
                                                 const float* __restrict__ w_in){
    extern __shared__ float sm[];
    float* xs = sm;                       // [32][512] (64KB), aliased as hs[32][8][64]
    u64*   wp = (u64*)(sm + 32*512);      // [64][16]  (8KB)
    int tile = blockIdx.x; int s = tile>>2, cg = tile&3;
    int oc0 = blockIdx.y*32; int b = blockIdx.z;
    int t = threadIdx.x;

    // pack weights: wp[c*16+j] = (w_in[oc0+2j][c], w_in[oc0+2j+1][c])
    for (int idx=t; idx<64*16; idx+=256){
        int c = idx>>4, j = idx&15;
        int o = oc0 + 2*j;
        wp[idx] = pk(w_in[o*DIMC + c], w_in[(o+1)*DIMC + c]);
    }

    int pxt = t & 127, ocg = t >> 7;            // 128 px-threads x 2 oc-groups
    int row = pxt >> 4, col4 = (pxt & 15) * 4;  // 4 consecutive cols, one row
    u64 acc[4][8];
    #pragma unroll
    for (int p=0;p<4;p++)
        #pragma unroll
        for (int j=0;j<8;j++) acc[p][j]=0ULL;

    const float* xb = x + (size_t)b*DIMC*HW + (s*8)*WWC + cg*64;
    for (int kc=0; kc<2; kc++){
        __syncthreads();
        for (int idx=t; idx<32*512; idx+=256){
            int c = idx>>9, px = idx&511, r = px>>6, cl = px&63;
            xs[idx] = xb[(size_t)(kc*32+c)*HW + r*WWC + cl];
        }
        __syncthreads();
        #pragma unroll 4
        for (int c=0;c<32;c++){
            float4 xv = *(const float4*)&xs[c*512 + pxt*4];
            u64 xp0 = pk(xv.x,xv.x), xp1 = pk(xv.y,xv.y);
            u64 xp2 = pk(xv.z,xv.z), xp3 = pk(xv.w,xv.w);
            const u64* wr = &wp[(kc*32+c)*16 + ocg*8];
            #pragma unroll
            for (int j=0;j<8;j++){
                u64 w = wr[j];
                fma2(acc[0][j], xp0, w);
                fma2(acc[1][j], xp1, w);
                fma2(acc[2][j], xp2, w);
                fma2(acc[3][j], xp3, w);
            }
        }
    }
    __syncthreads();   // all GEMM reads of xs complete before aliasing as hs

    // store h tile: hs[ocl][row][col]
    float* hs = xs;
    #pragma unroll
    for (int j=0;j<8;j++){
        int ocl0 = ocg*16 + 2*j;
        float2 v0=upk(acc[0][j]), v1=upk(acc[1][j]), v2=upk(acc[2][j]), v3=upk(acc[3][j]);
        float4 e  = make_float4(v0.x, v1.x, v2.x, v3.x);
        float4 o2 = make_float4(v0.y, v1.y, v2.y, v3.y);
        *(float4*)&hs[(ocl0*8 + row)*64 + col4]     = e;
        *(float4*)&hs[((ocl0+1)*8 + row)*64 + col4] = o2;
    }
    __syncthreads();

    // Phase 2: per-channel 8x8 circular conv. thread = (channel-quad, column)
    int chq = t >> 6;                 // 0..3
    int colc = t & 63;
    int n2 = colc & 7, p8 = (colc >> 3) * 8;
    float* ub = g_u + (size_t)(b*C2C + oc0)*HW + (s*8)*WWC + cg*64;
    for (int it=0; it<8; it++){
        int chl = it*4 + chq;         // local channel 0..31
        const u64* gptr = &g_pk[((size_t)(oc0+chl)*8 + n2)*32];
        u64 gpr[32];
        #pragma unroll
        for (int i2=0;i2<16;i2++){
            ulonglong2 vv = ((const ulonglong2*)gptr)[i2];
            gpr[2*i2]=vv.x; gpr[2*i2+1]=vv.y;
        }
        u64 acc2[8];
        #pragma unroll
        for (int n=0;n<8;n++) acc2[n]=0ULL;
        #pragma unroll
        for (int m1=0;m1<8;m1++){
            u64 xq[4];
            #pragma unroll
            for (int q=0;q<4;q++)
                xq[q] = *(const u64*)&hs[(chl*8+m1)*64 + p8 + 2*q];
            #pragma unroll
            for (int q=0;q<4;q++){
                #pragma unroll
                for (int n1=0;n1<8;n1++){
                    fma2(acc2[n1], xq[q], gpr[((n1-m1)&7)*4 + q]);
                }
            }
        }
        #pragma unroll
        for (int n1=0;n1<8;n1++){
            float2 v = upk(acc2[n1]);
            ub[(size_t)chl*HW + n1*WWC + colc] = v.x + v.y;
        }
    }
}

// ---------------- K3: depthwise 3x3 (SAME) + exact GELU gate -----------------
// Padded smem halo (zero cols 0 and 257) removes all inner bounds selects.
__global__ __launch_bounds__(256) void k3_dwgelu(const float* __restrict__ w_dw){
    __shared__ float su[2][18][258];
    int yt = blockIdx.x, i = blockIdx.y, b = blockIdx.z;
    int t = threadIdx.x;
    int y0 = yt*16;
    const float* u1 = g_u + (size_t)(b*C2C + i)*HW;
    const float* u2 = g_u + (size_t)(b*C2C + i + HFC)*HW;
    for (int rr=0; rr<18; rr++){
        int y = y0 + rr - 1;
        bool ok = (y>=0 && y<HH);
        su[0][rr][t+1] = ok ? u1[y*WWC + t] : 0.f;
        su[1][rr][t+1] = ok ? u2[y*WWC + t] : 0.f;
    }
    if (t < 18){ su[0][t][0]=0.f; su[0][t][257]=0.f; su[1][t][0]=0.f; su[1][t][257]=0.f; }
    __syncthreads();
    float wA[9], wB[9];
    #pragma unroll
    for (int k=0;k<9;k++){ wA[k]=w_dw[i*9+k]; wB[k]=w_dw[(i+HFC)*9+k]; }
    float* gb = g_g + (size_t)(b*HFC + i)*HW;
    for (int r=0;r<16;r++){
        float d1=0.f, d2=0.f;
        #pragma unroll
        for (int dy=0;dy<3;dy++){
            #pragma unroll
            for (int dx=0;dx<3;dx++){
                d1 = fmaf(wA[dy*3+dx], su[0][r+dy][t+dx], d1);
                d2 = fmaf(wB[dy*3+dx], su[1][r+dy][t+dx], d2);
            }
        }
        float ge = 0.5f*d1*(1.f + erff(d1*0.70710678118654752f));
        gb[(y0+r)*WWC + t] = ge*d2;
    }
}

// ---------------- K4: out-projection (register-tiled GEMM) -------------------
// Block: 256 px x all 64 out channels; thread: 4 px x 16 oc; k chunked by 32.
__global__ __launch_bounds__(256) void k4_outproj(float* __restrict__ out,
                                                  const float* __restrict__ w_out){
    extern __shared__ float sm[];
    float* gs = sm;                      // [32][256] (32KB)
    u64*   wp = (u64*)(sm + 32*256);     // [128][32] (32KB)
    int b = blockIdx.y; int px0 = blockIdx.x*256;
    int t = threadIdx.x;
    for (int idx=t; idx<128*32; idx+=256){
        int ii = idx>>5, j = idx&31;
        wp[idx] = pk(w_out[(2*j)*HFC + ii], w_out[(2*j+1)*HFC + ii]);
    }
    int pxt = t & 63, ocg = t >> 6;      // 64 px-threads x 4 oc-groups of 16
    u64 acc[4][8];
    #pragma unroll
    for (int p=0;p<4;p++)
        #pragma unroll
        for (int j=0;j<8;j++) acc[p][j]=0ULL;

    const float* gb = g_g + (size_t)b*HFC*HW + px0;
    for (int kc=0;kc<4;kc++){
        __syncthreads();
        for (int idx=t; idx<32*256; idx+=256){
            int ii = idx>>8, p = idx&255;
            gs[idx] = gb[(size_t)(kc*32+ii)*HW + p];
        }
        __syncthreads();
        #pragma unroll 4
        for (int ii=0; ii<32; ii++){
            float4 xv = *(const float4*)&gs[ii*256 + pxt*4];
            u64 xp0 = pk(xv.x,xv.x), xp1 = pk(xv.y,xv.y);
            u64 xp2 = pk(xv.z,xv.z), xp3 = pk(xv.w,xv.w);
            const u64* wr = &wp[(kc*32+ii)*32 + ocg*8];
            #pragma unroll
            for (int j=0;j<8;j++){
                u64 w = wr[j];
                fma2(acc[0][j], xp0, w);
                fma2(acc[1][j], xp1, w);
                fma2(acc[2][j], xp2, w);
                fma2(acc[3][j], xp3, w);
            }
        }
    }
    float* ob = out + (size_t)b*DIMC*HW + px0;
    #pragma unroll
    for (int j=0;j<8;j++){
        int jj = ocg*8 + j;
        float2 v0=upk(acc[0][j]), v1=upk(acc[1][j]), v2=upk(acc[2][j]), v3=upk(acc[3][j]);
        float4 e  = make_float4(v0.x, v1.x, v2.x, v3.x);
        float4 o2 = make_float4(v0.y, v1.y, v2.y, v3.y);
        *(float4*)&ob[(size_t)(2*jj)*HW   + pxt*4] = e;
        *(float4*)&ob[(size_t)(2*jj+1)*HW + pxt*4] = o2;
    }
}

// -----------------------------------------------------------------------------
extern "C" void kernel_launch(void* const* d_in, const int* in_sizes, int n_in,
                              void* d_out, int out_size){
    const float* x     = (const float*)d_in[0];
    const float* w_in  = (const float*)d_in[1];
    const float* w_dw  = (const float*)d_in[2];
    const float* filt  = (const float*)d_in[3];
    const float* w_out = (const float*)d_in[4];
    float* out = (float*)d_out;

    const int smem12 = 32*512*4 + 64*16*8;     // 73728 B
    const int smem4  = 32*256*4 + 128*32*8;    // 65536 B
    cudaFuncSetAttribute(k12_fused,  cudaFuncAttributeMaxDynamicSharedMemorySize, smem12);
    cudaFuncSetAttribute(k4_outproj, cudaFuncAttributeMaxDynamicSharedMemorySize, smem4);

    k0_spectral<<<256, 64>>>(filt);
    k12_fused  <<<dim3(128,8,4), 256, smem12>>>(x, w_in);
    k3_dwgelu  <<<dim3(16,128,4), 256>>>(w_dw);
    k4_outproj <<<dim3(256,4),    256, smem4>>>(out, w_out);
}